// round 14
// baseline (speedup 1.0000x reference)
#include <cuda_runtime.h>
#include <cstdint>
#include <cstddef>
#include <math.h>

// ---------------------------------------------------------------------------
// MoE layer, legacy tensor path (sm_103-safe: mma.sync only).
//   init -> router -> scan -> scatter
//   -> GEMM1 (gather raw x, in-loop tf32 cvt, +b1, gelu) -> g_H (tf32 bits)
//   -> GEMM2 (g_H @ W2 + b2, B converted in-loop)        -> g_Y
//   -> combine
// GEMMs: 128x128x32 tiles, warp tile 32x64 (4x2 warp grid), 3-stage cp.async,
// 2 CTAs/SM (smem 108KB). No separate conversion pass: tf32 rounding happens
// in registers (hides under tensor-pipe stalls), g_H stored pre-rounded.
// Launches: 0:init 1:router 2:scan 3:scatter 4:GEMM1 5:GEMM2 (ncu -s 5) 6:combine
// ---------------------------------------------------------------------------

constexpr int HID_ = 1024;
constexpr int FFN_ = 4096;
constexpr int NE_  = 8;
constexpr int T_   = 4096;

constexpr int BM = 128, BN = 128, BK = 32;
constexpr int STAGES = 3;
constexpr int ASTRIDE = 36;          // 32 + 4 pad: af banks (4g+t) all distinct
constexpr int BSTRIDE = 136;         // 128 + 8: bf banks (8t+g) all distinct
constexpr int MAX_SLOTS = T_ * 2 + NE_ * BM;   // 9216
constexpr int ROW_TILES = MAX_SLOTS / BM;      // 72

constexpr uint32_t ABUF = sizeof(float) * BM * ASTRIDE;   // 18432 B
constexpr uint32_t BBUF = sizeof(float) * BK * BSTRIDE;   // 17408 B
constexpr int SOFF_BIAS = STAGES * (int)(ABUF + BBUF);    // 107520
constexpr int SMEM_BYTES = SOFF_BIAS + BN * 4;            // 108032 -> 2 CTAs/SM

// ---------------- scratch ---------------------------------------------------
__device__ float g_H[(size_t)MAX_SLOTS * FFN_];     // GEMM1 out (tf32 bits)
__device__ float g_Y[(size_t)MAX_SLOTS * HID_];     // GEMM2 out (f32)
__device__ int   g_slot_tok[MAX_SLOTS];
__device__ int   g_tok_slot[T_ * 2];
__device__ int   g_top_i[T_ * 2];
__device__ float g_top_w[T_ * 2];
__device__ int   g_counts[NE_];
__device__ int   g_fill[NE_];
__device__ int   g_poff[NE_ + 1];

// ---------------- helpers ---------------------------------------------------
__device__ __forceinline__ uint32_t f2tf32(float f) {
    uint32_t r;
    asm("cvt.rna.tf32.f32 %0, %1;" : "=r"(r) : "f"(f));
    return r;
}
__device__ __forceinline__ void mma_tf32(float* c, const uint32_t* a, const uint32_t* b) {
    asm volatile(
        "mma.sync.aligned.m16n8k8.row.col.f32.tf32.tf32.f32 "
        "{%0,%1,%2,%3}, {%4,%5,%6,%7}, {%8,%9}, {%0,%1,%2,%3};"
        : "+f"(c[0]), "+f"(c[1]), "+f"(c[2]), "+f"(c[3])
        : "r"(a[0]), "r"(a[1]), "r"(a[2]), "r"(a[3]),
          "r"(b[0]), "r"(b[1]));
}
__device__ __forceinline__ void cp16(uint32_t smem_addr, const void* gptr, int src_bytes) {
    asm volatile("cp.async.cg.shared.global [%0], [%1], 16, %2;"
                 :: "r"(smem_addr), "l"(gptr), "r"(src_bytes) : "memory");
}
__device__ __forceinline__ float gelu_exact(float v) {
    return 0.5f * v * (1.0f + erff(v * 0.70710678118654752440f));
}

// ---------------- init / router / scan / scatter ----------------------------
__global__ void init_kernel() {
    int i = blockIdx.x * blockDim.x + threadIdx.x;
    if (i < MAX_SLOTS) g_slot_tok[i] = -1;
    if (i < NE_) { g_counts[i] = 0; g_fill[i] = 0; }
}

__global__ void router_kernel(const float* __restrict__ x, const float* __restrict__ Wr) {
    int gw = (blockIdx.x * blockDim.x + threadIdx.x) >> 5;
    int lane = threadIdx.x & 31;
    if (gw >= T_) return;
    const float* xr = x + (size_t)gw * HID_;
    float acc[NE_];
#pragma unroll
    for (int e = 0; e < NE_; e++) acc[e] = 0.f;
    for (int j = lane; j < HID_; j += 32) {
        float xv = xr[j];
        const float4* w4 = (const float4*)(Wr + (size_t)j * NE_);
        float4 a = w4[0], b = w4[1];
        acc[0] += xv * a.x; acc[1] += xv * a.y; acc[2] += xv * a.z; acc[3] += xv * a.w;
        acc[4] += xv * b.x; acc[5] += xv * b.y; acc[6] += xv * b.z; acc[7] += xv * b.w;
    }
#pragma unroll
    for (int off = 16; off > 0; off >>= 1)
#pragma unroll
        for (int e = 0; e < NE_; e++)
            acc[e] += __shfl_xor_sync(0xffffffffu, acc[e], off);
    if (lane == 0) {
        int i0 = 0;
#pragma unroll
        for (int e = 1; e < NE_; e++) if (acc[e] > acc[i0]) i0 = e;   // ties keep low idx
        int i1 = (i0 == 0) ? 1 : 0;
#pragma unroll
        for (int e = 0; e < NE_; e++) if (e != i0 && acc[e] > acc[i1]) i1 = e;
        float d = acc[i1] - acc[i0];
        float w1v = 1.f / (1.f + expf(-d));      // sigmoid(l1 - l0) == renorm top-2 softmax
        float w0v = 1.f - w1v;
        g_top_i[2 * gw] = i0;  g_top_i[2 * gw + 1] = i1;
        g_top_w[2 * gw] = w0v; g_top_w[2 * gw + 1] = w1v;
        atomicAdd(&g_counts[i0], 1);
        atomicAdd(&g_counts[i1], 1);
    }
}

__global__ void scan_kernel() {
    if (threadIdx.x == 0) {
        int o = 0;
#pragma unroll
        for (int e = 0; e < NE_; e++) {
            g_poff[e] = o;
            o += ((g_counts[e] + BM - 1) / BM) * BM;
        }
        g_poff[NE_] = o;
    }
}

__global__ void scatter_kernel() {
    int tk = blockIdx.x * blockDim.x + threadIdx.x;
    if (tk >= T_ * 2) return;
    int e = g_top_i[tk];
    int p = atomicAdd(&g_fill[e], 1);
    int s = g_poff[e] + p;
    g_slot_tok[s] = tk >> 1;
    g_tok_slot[tk] = s;
}

// ---------------- grouped GEMM (tf32 mma.sync, in-loop cvt, 2 CTA/SM) -------
// FFN1=true : A = gathered raw x (KD=1024, CVT_A), B = W1 raw (CVT_B),
//             out = tf32(gelu(A@B + b1)) -> g_H
// FFN1=false: A = g_H (KD=4096, already tf32 bits, no CVT), B = W2 raw (CVT_B),
//             out = A@B + b2 -> g_Y
template <int KD, int ND, bool FFN1, bool CVT_A, bool CVT_B>
__global__ void __launch_bounds__(256, 2)
moe_gemm_kernel(const float* __restrict__ Asrc,
                const float* __restrict__ W,
                const float* __restrict__ bias) {
    extern __shared__ float smem_dyn[];
    float* As_base = smem_dyn;                               // [STAGES][BM][ASTRIDE]
    float* Bs_base = smem_dyn + STAGES * BM * ASTRIDE;       // [STAGES][BK][BSTRIDE]
    float* bias_s  = smem_dyn + SOFF_BIAS / 4;               // [BN]

    const int row0 = blockIdx.x * BM;
    if (row0 >= g_poff[NE_]) return;
    int e = 0;
#pragma unroll
    for (int i = 1; i < NE_; i++) if (g_poff[i] <= row0) e = i;

    const float* Ap = FFN1 ? Asrc : g_H;
    float*       Op = FFN1 ? g_H : g_Y;
    const float* Wb = W + (size_t)e * KD * ND;
    const int n0 = blockIdx.y * BN;
    const int tid = threadIdx.x;

    if (tid < BN) bias_s[tid] = bias[(size_t)e * ND + n0 + tid];

    // ---- per-thread cp.async assignments (stage-0 relative) ----
    // A: 128 rows x 8 quads = 1024 quads, 4 per thread
    const float* agp[4]; uint32_t asmem[4]; int apred[4];
#pragma unroll
    for (int it = 0; it < 4; it++) {
        int q = tid + it * 256;
        int r = q >> 3, c4 = q & 7;
        int s = row0 + r;
        int pred = 16;
        const float* gp;
        if (FFN1) {
            int tok = g_slot_tok[s];
            if (tok < 0) { pred = 0; tok = 0; }   // pad row -> cp.async zero-fill
            gp = Ap + (size_t)tok * KD;
        } else {
            gp = Ap + (size_t)s * KD;
        }
        agp[it] = gp + c4 * 4;
        apred[it] = pred;
        asmem[it] = (uint32_t)__cvta_generic_to_shared(&As_base[r * ASTRIDE + c4 * 4]);
    }
    // B: 32 k-rows x 32 quads = 1024 quads, 4 per thread
    const float* bgp[4]; uint32_t bsmem[4];
#pragma unroll
    for (int it = 0; it < 4; it++) {
        int q = tid + it * 256;
        int k = q >> 5, nq = q & 31;
        bgp[it] = Wb + (size_t)k * ND + n0 + nq * 4;
        bsmem[it] = (uint32_t)__cvta_generic_to_shared(&Bs_base[k * BSTRIDE + nq * 4]);
    }

    const int lane = tid & 31, warp = tid >> 5;
    const int wm = warp >> 1, wn = warp & 1;   // 4 x 2 warp grid; 32x64 per warp
    const int gg = lane >> 2, tt = lane & 3;

    float acc[2][8][4];
#pragma unroll
    for (int a = 0; a < 2; a++)
#pragma unroll
        for (int b = 0; b < 8; b++)
#pragma unroll
            for (int c = 0; c < 4; c++) acc[a][b][c] = 0.f;

    const int KT = KD / BK;   // 32 (GEMM1) or 128 (GEMM2)

    // prefetch stages 0,1
#pragma unroll
    for (int s = 0; s < STAGES - 1; s++) {
#pragma unroll
        for (int it = 0; it < 4; it++)
            cp16(asmem[it] + s * ABUF, agp[it] + (size_t)s * BK, apred[it]);
#pragma unroll
        for (int it = 0; it < 4; it++)
            cp16(bsmem[it] + s * BBUF, bgp[it] + (size_t)s * BK * ND, 16);
        asm volatile("cp.async.commit_group;" ::: "memory");
    }

    for (int kt = 0; kt < KT; ++kt) {
        if (kt + 1 < KT) asm volatile("cp.async.wait_group 1;" ::: "memory");
        else             asm volatile("cp.async.wait_group 0;" ::: "memory");
        __syncthreads();   // single barrier per k-iter; buf (kt+2)%3 reusable after it

        if (kt + 2 < KT) {
            const int sb = (kt + 2) % STAGES;
            const uint32_t ao = sb * ABUF, bo = sb * BBUF;
#pragma unroll
            for (int it = 0; it < 4; it++)
                cp16(asmem[it] + ao, agp[it] + (size_t)(kt + 2) * BK, apred[it]);
#pragma unroll
            for (int it = 0; it < 4; it++)
                cp16(bsmem[it] + bo, bgp[it] + (size_t)(kt + 2) * BK * ND, 16);
            asm volatile("cp.async.commit_group;" ::: "memory");
        }

        const int buf = kt % STAGES;
        const float* Asb = As_base + buf * BM * ASTRIDE;
        const float* Bsb = Bs_base + buf * BK * BSTRIDE;
#pragma unroll
        for (int kk = 0; kk < BK; kk += 8) {
            uint32_t af[2][4], bf[8][2];
#pragma unroll
            for (int mi = 0; mi < 2; mi++) {
                int r = wm * 32 + mi * 16 + gg;
                float a0 = Asb[r * ASTRIDE + kk + tt];
                float a1 = Asb[(r + 8) * ASTRIDE + kk + tt];
                float a2 = Asb[r * ASTRIDE + kk + tt + 4];
                float a3 = Asb[(r + 8) * ASTRIDE + kk + tt + 4];
                if (CVT_A) {
                    af[mi][0] = f2tf32(a0); af[mi][1] = f2tf32(a1);
                    af[mi][2] = f2tf32(a2); af[mi][3] = f2tf32(a3);
                } else {
                    af[mi][0] = __float_as_uint(a0); af[mi][1] = __float_as_uint(a1);
                    af[mi][2] = __float_as_uint(a2); af[mi][3] = __float_as_uint(a3);
                }
            }
#pragma unroll
            for (int ni = 0; ni < 8; ni++) {
                int n = wn * 64 + ni * 8 + gg;
                float b0 = Bsb[(kk + tt) * BSTRIDE + n];
                float b1 = Bsb[(kk + tt + 4) * BSTRIDE + n];
                if (CVT_B) {
                    bf[ni][0] = f2tf32(b0); bf[ni][1] = f2tf32(b1);
                } else {
                    bf[ni][0] = __float_as_uint(b0); bf[ni][1] = __float_as_uint(b1);
                }
            }
#pragma unroll
            for (int mi = 0; mi < 2; mi++)
#pragma unroll
                for (int ni = 0; ni < 8; ni++)
                    mma_tf32(acc[mi][ni], af[mi], bf[ni]);
        }
    }

    // epilogue
#pragma unroll
    for (int mi = 0; mi < 2; mi++) {
#pragma unroll
        for (int half = 0; half < 2; half++) {
            int r = row0 + wm * 32 + mi * 16 + gg + half * 8;
#pragma unroll
            for (int ni = 0; ni < 8; ni++) {
                int colL = wn * 64 + ni * 8 + 2 * tt;
                float v0 = acc[mi][ni][half * 2 + 0] + bias_s[colL];
                float v1 = acc[mi][ni][half * 2 + 1] + bias_s[colL + 1];
                if (FFN1) {
                    // store pre-rounded tf32 bits so GEMM2 skips A conversion
                    v0 = __uint_as_float(f2tf32(gelu_exact(v0)));
                    v1 = __uint_as_float(f2tf32(gelu_exact(v1)));
                }
                float2 v; v.x = v0; v.y = v1;
                *(float2*)&Op[(size_t)r * ND + n0 + colL] = v;
            }
        }
    }
}

// ---------------- combine ----------------------------------------------------
__global__ void combine_kernel(float* __restrict__ out) {
    int i = blockIdx.x * blockDim.x + threadIdx.x;
    if (i >= T_ * HID_ / 4) return;
    int t = i / (HID_ / 4);
    int c4 = i % (HID_ / 4);
    int s0 = g_tok_slot[2 * t], s1 = g_tok_slot[2 * t + 1];
    float w0 = g_top_w[2 * t], w1 = g_top_w[2 * t + 1];
    float4 y0 = ((const float4*)(g_Y + (size_t)s0 * HID_))[c4];
    float4 y1 = ((const float4*)(g_Y + (size_t)s1 * HID_))[c4];
    float4 r;
    r.x = w0 * y0.x + w1 * y1.x;
    r.y = w0 * y0.y + w1 * y1.y;
    r.z = w0 * y0.z + w1 * y1.z;
    r.w = w0 * y0.w + w1 * y1.w;
    ((float4*)(out + (size_t)t * HID_))[c4] = r;
}

// ---------------- launch ----------------------------------------------------
extern "C" void kernel_launch(void* const* d_in, const int* in_sizes, int n_in,
                              void* d_out, int out_size) {
    (void)in_sizes; (void)n_in; (void)out_size;
    const float* x  = (const float*)d_in[0];
    const float* Wr = (const float*)d_in[1];
    const float* W1 = (const float*)d_in[2];
    const float* b1 = (const float*)d_in[3];
    const float* W2 = (const float*)d_in[4];
    const float* b2 = (const float*)d_in[5];
    float* out = (float*)d_out;

    cudaFuncSetAttribute(moe_gemm_kernel<HID_, FFN_, true, true, true>,
                         cudaFuncAttributeMaxDynamicSharedMemorySize, SMEM_BYTES);
    cudaFuncSetAttribute(moe_gemm_kernel<FFN_, HID_, false, false, true>,
                         cudaFuncAttributeMaxDynamicSharedMemorySize, SMEM_BYTES);

    // launch indices: 0:init 1:router 2:scan 3:scatter 4:GEMM1 5:GEMM2 (ncu -s 5)
    init_kernel<<<(MAX_SLOTS + 255) / 256, 256>>>();
    router_kernel<<<(T_ * 32 + 255) / 256, 256>>>(x, Wr);
    scan_kernel<<<1, 32>>>();
    scatter_kernel<<<(T_ * 2 + 255) / 256, 256>>>();

    moe_gemm_kernel<HID_, FFN_, true, true, true>
        <<<dim3(ROW_TILES, FFN_ / BN), 256, SMEM_BYTES>>>(x, W1, b1);
    moe_gemm_kernel<FFN_, HID_, false, false, true>
        <<<dim3(ROW_TILES, HID_ / BN), 256, SMEM_BYTES>>>(x, W2, b2);

    combine_kernel<<<(T_ * HID_ / 4 + 255) / 256, 256>>>(out);
}

// round 15
// speedup vs baseline: 1.5680x; 1.5680x over previous
#include <cuda_runtime.h>
#include <cuda_fp16.h>
#include <cstdint>
#include <cstddef>
#include <math.h>

// ---------------------------------------------------------------------------
// MoE layer, legacy tensor path, fp16 mma.sync.m16n8k16 (f32 accumulate).
//   prep(init + x->fp16 + W1,W2 transpose->[n][k] fp16, ONE launch)
//   -> router -> scan_scatter(1 blk)
//   -> GEMM1 (gather xh, fp16 mma, +b1, gelu) -> g_Hh (fp16)   [launch #3]
//   -> GEMM2 (g_Hh @ W2t + b2)               -> g_Y  (f32)
//   -> combine
// GEMMs: 128x128x32 tiles, warp tile 32x64, 3-stage cp.async, 62KB smem/CTA.
// fp16 mantissa == tf32 mantissa (10 bits) -> same error model as tf32 path.
// ---------------------------------------------------------------------------

constexpr int HID_ = 1024;
constexpr int FFN_ = 4096;
constexpr int NE_  = 8;
constexpr int T_   = 4096;

constexpr int BM = 128, BN = 128, BK = 32;     // BK in halves (k-elements)
constexpr int STAGES = 3;
constexpr int STRD = 40;                       // halves per smem row (32 + 8 pad) = 80B
constexpr int MAX_SLOTS = T_ * 2 + NE_ * BM;   // 9216
constexpr int ROW_TILES = MAX_SLOTS / BM;      // 72

constexpr uint32_t ABUF = 2u * BM * STRD;      // 10240 B per A stage
constexpr uint32_t BBUF = 2u * BN * STRD;      // 10240 B per B stage
constexpr int SOFF_BIAS = STAGES * (int)(ABUF + BBUF);    // 61440
constexpr int SMEM_BYTES = SOFF_BIAS + BN * 4;            // 61952

// prep grid segmentation
constexpr int TILES1 = NE_ * (HID_ / 32) * (FFN_ / 32);   // 32768 (W1: K=HID,N=FFN)
constexpr int TILES2 = NE_ * (FFN_ / 32) * (HID_ / 32);   // 32768 (W2: K=FFN,N=HID)
constexpr int XB     = T_ * HID_ / 1024;                  // 4096 (1024 elems/blk)
constexpr int IB     = (MAX_SLOTS + 255) / 256;           // 36
constexpr int PREP_GRID = TILES1 + TILES2 + XB + IB;

// ---------------- scratch ---------------------------------------------------
__device__ __half g_xh[(size_t)T_ * HID_];              // x  -> fp16
__device__ __half g_W1t[(size_t)NE_ * FFN_ * HID_];     // W1^T: [e][n(FFN)][k(HID)]
__device__ __half g_W2t[(size_t)NE_ * HID_ * FFN_];     // W2^T: [e][n(HID)][k(FFN)]
__device__ __half g_Hh[(size_t)MAX_SLOTS * FFN_];       // GEMM1 out (fp16)
__device__ float  g_Y[(size_t)MAX_SLOTS * HID_];        // GEMM2 out (f32)
__device__ int    g_slot_tok[MAX_SLOTS];
__device__ int    g_tok_slot[T_ * 2];
__device__ int    g_top_i[T_ * 2];
__device__ float  g_top_w[T_ * 2];
__device__ int    g_counts[NE_];
__device__ int    g_poff[NE_ + 1];

// ---------------- helpers ---------------------------------------------------
__device__ __forceinline__ void mma_f16(float* c, const uint32_t* a, const uint32_t* b) {
    asm volatile(
        "mma.sync.aligned.m16n8k16.row.col.f32.f16.f16.f32 "
        "{%0,%1,%2,%3}, {%4,%5,%6,%7}, {%8,%9}, {%0,%1,%2,%3};"
        : "+f"(c[0]), "+f"(c[1]), "+f"(c[2]), "+f"(c[3])
        : "r"(a[0]), "r"(a[1]), "r"(a[2]), "r"(a[3]),
          "r"(b[0]), "r"(b[1]));
}
__device__ __forceinline__ void cp16(uint32_t smem_addr, const void* gptr, int src_bytes) {
    asm volatile("cp.async.cg.shared.global [%0], [%1], 16, %2;"
                 :: "r"(smem_addr), "l"(gptr), "r"(src_bytes) : "memory");
}
__device__ __forceinline__ float gelu_exact(float v) {
    return 0.5f * v * (1.0f + erff(v * 0.70710678118654752440f));
}

// ---------------- prep: init + cvt x + transpose-cvt W1,W2 (one launch) -----
__device__ __forceinline__ void transpose_tile(const float* __restrict__ W,
                                               __half* __restrict__ Wt,
                                               int K, int N, int tileIdx,
                                               __half (*tile)[33], int tid) {
    const int tilesPerE = (K / 32) * (N / 32);
    const int e  = tileIdx / tilesPerE;
    const int rm = tileIdx % tilesPerE;
    const int k0 = (rm / (N / 32)) * 32;
    const int n0 = (rm % (N / 32)) * 32;
    const float* src = W + (size_t)e * K * N;
    __half* dst = Wt + (size_t)e * N * K;
    const int tx = tid & 31, ty = tid >> 5;         // 32 x 8
#pragma unroll
    for (int j = 0; j < 4; j++) {
        int k = k0 + ty + 8 * j;
        tile[ty + 8 * j][tx] = __float2half_rn(src[(size_t)k * N + n0 + tx]);
    }
    __syncthreads();
#pragma unroll
    for (int j = 0; j < 4; j++) {
        int n = n0 + ty + 8 * j;
        dst[(size_t)n * K + k0 + tx] = tile[tx][ty + 8 * j];
    }
}

__global__ void prep_kernel(const float* __restrict__ x,
                            const float* __restrict__ W1,
                            const float* __restrict__ W2) {
    __shared__ __half tile[32][33];
    const int bid = blockIdx.x, tid = threadIdx.x;
    if (bid < TILES1) {
        transpose_tile(W1, g_W1t, HID_, FFN_, bid, tile, tid);
    } else if (bid < TILES1 + TILES2) {
        transpose_tile(W2, g_W2t, FFN_, HID_, bid - TILES1, tile, tid);
    } else if (bid < TILES1 + TILES2 + XB) {
        int i = (bid - TILES1 - TILES2) * 256 + tid;      // float4 index
        const float4 v = ((const float4*)x)[i];
        __half2* out = (__half2*)g_xh;
        out[i * 2]     = __floats2half2_rn(v.x, v.y);
        out[i * 2 + 1] = __floats2half2_rn(v.z, v.w);
    } else {
        int i = (bid - TILES1 - TILES2 - XB) * 256 + tid;
        if (i < MAX_SLOTS) g_slot_tok[i] = -1;
        if (i < NE_) g_counts[i] = 0;
    }
}

// ---------------- router (unchanged logic) ----------------------------------
__global__ void router_kernel(const float* __restrict__ x, const float* __restrict__ Wr) {
    int gw = (blockIdx.x * blockDim.x + threadIdx.x) >> 5;
    int lane = threadIdx.x & 31;
    if (gw >= T_) return;
    const float* xr = x + (size_t)gw * HID_;
    float acc[NE_];
#pragma unroll
    for (int e = 0; e < NE_; e++) acc[e] = 0.f;
    for (int j = lane; j < HID_; j += 32) {
        float xv = xr[j];
        const float4* w4 = (const float4*)(Wr + (size_t)j * NE_);
        float4 a = w4[0], b = w4[1];
        acc[0] += xv * a.x; acc[1] += xv * a.y; acc[2] += xv * a.z; acc[3] += xv * a.w;
        acc[4] += xv * b.x; acc[5] += xv * b.y; acc[6] += xv * b.z; acc[7] += xv * b.w;
    }
#pragma unroll
    for (int off = 16; off > 0; off >>= 1)
#pragma unroll
        for (int e = 0; e < NE_; e++)
            acc[e] += __shfl_xor_sync(0xffffffffu, acc[e], off);
    if (lane == 0) {
        int i0 = 0;
#pragma unroll
        for (int e = 1; e < NE_; e++) if (acc[e] > acc[i0]) i0 = e;   // ties keep low idx
        int i1 = (i0 == 0) ? 1 : 0;
#pragma unroll
        for (int e = 0; e < NE_; e++) if (e != i0 && acc[e] > acc[i1]) i1 = e;
        float d = acc[i1] - acc[i0];
        float w1v = 1.f / (1.f + expf(-d));      // sigmoid == renorm top-2 softmax
        float w0v = 1.f - w1v;
        g_top_i[2 * gw] = i0;  g_top_i[2 * gw + 1] = i1;
        g_top_w[2 * gw] = w0v; g_top_w[2 * gw + 1] = w1v;
        atomicAdd(&g_counts[i0], 1);
        atomicAdd(&g_counts[i1], 1);
    }
}

// ---------------- scan + scatter (one block) --------------------------------
__global__ void scan_scatter_kernel() {
    __shared__ int fill_s[NE_];
    __shared__ int poff_s[NE_ + 1];
    const int tid = threadIdx.x;
    if (tid == 0) {
        int o = 0;
#pragma unroll
        for (int e = 0; e < NE_; e++) {
            poff_s[e] = o; g_poff[e] = o;
            o += ((g_counts[e] + BM - 1) / BM) * BM;
        }
        poff_s[NE_] = o; g_poff[NE_] = o;
    }
    if (tid < NE_) fill_s[tid] = 0;
    __syncthreads();
    for (int tk = tid; tk < T_ * 2; tk += 256) {
        int e = g_top_i[tk];
        int p = atomicAdd(&fill_s[e], 1);
        int s = poff_s[e] + p;
        g_slot_tok[s] = tk >> 1;
        g_tok_slot[tk] = s;
    }
}

// ---------------- grouped GEMM (fp16 m16n8k16, warp tile 32x64) -------------
// FFN1=true : A = gathered g_xh rows (KD=1024), B = g_W1t[e] [n][k],
//             out = fp16(gelu(A@B + b1)) -> g_Hh
// FFN1=false: A = g_Hh rows (KD=4096),          B = g_W2t[e] [n][k],
//             out = A@B + b2 -> g_Y (f32)
template <int KD, int ND, bool FFN1>
__global__ void __launch_bounds__(256, 2)
moe_gemm_kernel(const __half* __restrict__ Aall,
                const __half* __restrict__ Wt,
                const float* __restrict__ bias) {
    extern __shared__ char smem_raw[];
    __half* As_base = (__half*)smem_raw;                          // [STAGES][BM][STRD]
    __half* Bs_base = (__half*)(smem_raw + STAGES * (int)ABUF);   // [STAGES][BN][STRD]
    float*  bias_s  = (float*)(smem_raw + SOFF_BIAS);             // [BN]

    const int row0 = blockIdx.x * BM;
    if (row0 >= g_poff[NE_]) return;
    int e = 0;
#pragma unroll
    for (int i = 1; i < NE_; i++) if (g_poff[i] <= row0) e = i;

    const __half* Wb = Wt + (size_t)e * KD * ND;   // [ND][KD]
    const int n0 = blockIdx.y * BN;
    const int tid = threadIdx.x;

    if (tid < BN) bias_s[tid] = bias[(size_t)e * ND + n0 + tid];

    // ---- cp.async assignments: rows of 32 halves = 4 x 16B chunks ----
    // A: 128 rows x 4 chunks = 512, 2 per thread
    const __half* agp[2]; uint32_t asmem[2]; int apred[2];
#pragma unroll
    for (int it = 0; it < 2; it++) {
        int q = tid + it * 256;
        int r = q >> 2, c4 = q & 3;
        int s = row0 + r;
        int pred = 16;
        const __half* gp;
        if (FFN1) {
            int tok = g_slot_tok[s];
            if (tok < 0) { pred = 0; tok = 0; }   // pad row -> zero-fill
            gp = Aall + (size_t)tok * KD;
        } else {
            gp = Aall + (size_t)s * KD;
        }
        agp[it] = gp + c4 * 8;
        apred[it] = pred;
        asmem[it] = (uint32_t)__cvta_generic_to_shared(&As_base[r * STRD + c4 * 8]);
    }
    // B: 128 n-rows x 4 chunks = 512, 2 per thread
    const __half* bgp[2]; uint32_t bsmem[2];
#pragma unroll
    for (int it = 0; it < 2; it++) {
        int q = tid + it * 256;
        int r = q >> 2, c4 = q & 3;
        bgp[it] = Wb + (size_t)(n0 + r) * KD + c4 * 8;
        bsmem[it] = (uint32_t)__cvta_generic_to_shared(&Bs_base[r * STRD + c4 * 8]);
    }

    const int lane = tid & 31, warp = tid >> 5;
    const int wm = warp >> 1, wn = warp & 1;   // 4 x 2 warp grid; 32x64 per warp
    const int gg = lane >> 2, tt = lane & 3;

    float acc[2][8][4];
#pragma unroll
    for (int a = 0; a < 2; a++)
#pragma unroll
        for (int b = 0; b < 8; b++)
#pragma unroll
            for (int c = 0; c < 4; c++) acc[a][b][c] = 0.f;

    const int KT = KD / BK;   // 32 (GEMM1) or 128 (GEMM2)

    // prefetch stages 0,1
#pragma unroll
    for (int s = 0; s < STAGES - 1; s++) {
#pragma unroll
        for (int it = 0; it < 2; it++)
            cp16(asmem[it] + s * ABUF, agp[it] + (size_t)s * BK, apred[it]);
#pragma unroll
        for (int it = 0; it < 2; it++)
            cp16(bsmem[it] + s * BBUF, bgp[it] + (size_t)s * BK, 16);
        asm volatile("cp.async.commit_group;" ::: "memory");
    }

    for (int kt = 0; kt < KT; ++kt) {
        if (kt + 1 < KT) asm volatile("cp.async.wait_group 1;" ::: "memory");
        else             asm volatile("cp.async.wait_group 0;" ::: "memory");
        __syncthreads();   // single barrier per k-iter; buf (kt+2)%3 reusable after it

        if (kt + 2 < KT) {
            const int sb = (kt + 2) % STAGES;
            const uint32_t ao = sb * ABUF, bo = sb * BBUF;
#pragma unroll
            for (int it = 0; it < 2; it++)
                cp16(asmem[it] + ao, agp[it] + (size_t)(kt + 2) * BK, apred[it]);
#pragma unroll
            for (int it = 0; it < 2; it++)
                cp16(bsmem[it] + bo, bgp[it] + (size_t)(kt + 2) * BK, 16);
            asm volatile("cp.async.commit_group;" ::: "memory");
        }

        const int buf = kt % STAGES;
        const __half* Asb = As_base + buf * BM * STRD;
        const __half* Bsb = Bs_base + buf * BN * STRD;
#pragma unroll
        for (int kk = 0; kk < BK; kk += 16) {     // two m16n8k16 steps per buffer
            uint32_t af[2][4], bf[8][2];
#pragma unroll
            for (int mi = 0; mi < 2; mi++) {
                int r = wm * 32 + mi * 16 + gg;
                af[mi][0] = *(const uint32_t*)&Asb[r * STRD + kk + 2 * tt];
                af[mi][1] = *(const uint32_t*)&Asb[(r + 8) * STRD + kk + 2 * tt];
                af[mi][2] = *(const uint32_t*)&Asb[r * STRD + kk + 2 * tt + 8];
                af[mi][3] = *(const uint32_t*)&Asb[(r + 8) * STRD + kk + 2 * tt + 8];
            }
#pragma unroll
            for (int ni = 0; ni < 8; ni++) {
                int n = wn * 64 + ni * 8 + gg;
                bf[ni][0] = *(const uint32_t*)&Bsb[n * STRD + kk + 2 * tt];
                bf[ni][1] = *(const uint32_t*)&Bsb[n * STRD + kk + 2 * tt + 8];
            }
#pragma unroll
            for (int mi = 0; mi < 2; mi++)
#pragma unroll
                for (int ni = 0; ni < 8; ni++)
                    mma_f16(acc[mi][ni], af[mi], bf[ni]);
        }
    }

    // epilogue: c0/c1 -> row gg cols 2tt/2tt+1 ; c2/c3 -> row gg+8
#pragma unroll
    for (int mi = 0; mi < 2; mi++) {
#pragma unroll
        for (int half = 0; half < 2; half++) {
            int r = row0 + wm * 32 + mi * 16 + gg + half * 8;
#pragma unroll
            for (int ni = 0; ni < 8; ni++) {
                int colL = wn * 64 + ni * 8 + 2 * tt;
                float v0 = acc[mi][ni][half * 2 + 0] + bias_s[colL];
                float v1 = acc[mi][ni][half * 2 + 1] + bias_s[colL + 1];
                if (FFN1) {
                    __half2 hv = __floats2half2_rn(gelu_exact(v0), gelu_exact(v1));
                    *(__half2*)&g_Hh[(size_t)r * ND + n0 + colL] = hv;
                } else {
                    float2 v; v.x = v0; v.y = v1;
                    *(float2*)&g_Y[(size_t)r * ND + n0 + colL] = v;
                }
            }
        }
    }
}

// ---------------- combine ----------------------------------------------------
__global__ void combine_kernel(float* __restrict__ out) {
    int i = blockIdx.x * blockDim.x + threadIdx.x;
    if (i >= T_ * HID_ / 4) return;
    int t = i / (HID_ / 4);
    int c4 = i % (HID_ / 4);
    int s0 = g_tok_slot[2 * t], s1 = g_tok_slot[2 * t + 1];
    float w0 = g_top_w[2 * t], w1 = g_top_w[2 * t + 1];
    float4 y0 = ((const float4*)(g_Y + (size_t)s0 * HID_))[c4];
    float4 y1 = ((const float4*)(g_Y + (size_t)s1 * HID_))[c4];
    float4 r;
    r.x = w0 * y0.x + w1 * y1.x;
    r.y = w0 * y0.y + w1 * y1.y;
    r.z = w0 * y0.z + w1 * y1.z;
    r.w = w0 * y0.w + w1 * y1.w;
    ((float4*)(out + (size_t)t * HID_))[c4] = r;
}

// ---------------- launch ----------------------------------------------------
extern "C" void kernel_launch(void* const* d_in, const int* in_sizes, int n_in,
                              void* d_out, int out_size) {
    (void)in_sizes; (void)n_in; (void)out_size;
    const float* x  = (const float*)d_in[0];
    const float* Wr = (const float*)d_in[1];
    const float* W1 = (const float*)d_in[2];
    const float* b1 = (const float*)d_in[3];
    const float* W2 = (const float*)d_in[4];
    const float* b2 = (const float*)d_in[5];
    float* out = (float*)d_out;

    cudaFuncSetAttribute(moe_gemm_kernel<HID_, FFN_, true>,
                         cudaFuncAttributeMaxDynamicSharedMemorySize, SMEM_BYTES);
    cudaFuncSetAttribute(moe_gemm_kernel<FFN_, HID_, false>,
                         cudaFuncAttributeMaxDynamicSharedMemorySize, SMEM_BYTES);

    __half* xh;  cudaGetSymbolAddress((void**)&xh,  g_xh);
    __half* w1t; cudaGetSymbolAddress((void**)&w1t, g_W1t);
    __half* w2t; cudaGetSymbolAddress((void**)&w2t, g_W2t);
    __half* hh;  cudaGetSymbolAddress((void**)&hh,  g_Hh);

    // launches: 0:prep 1:router 2:scan_scatter 3:GEMM1 4:GEMM2 5:combine
    prep_kernel<<<PREP_GRID, 256>>>(x, W1, W2);
    router_kernel<<<(T_ * 32 + 255) / 256, 256>>>(x, Wr);
    scan_scatter_kernel<<<1, 256>>>();

    moe_gemm_kernel<HID_, FFN_, true>
        <<<dim3(ROW_TILES, FFN_ / BN), 256, SMEM_BYTES>>>(xh, w1t, b1);
    moe_gemm_kernel<FFN_, HID_, false>
        <<<dim3(ROW_TILES, HID_ / BN), 256, SMEM_BYTES>>>(hh, w2t, b2);

    combine_kernel<<<(T_ * HID_ / 4 + 255) / 256, 256>>>(out);
}

// round 16
// speedup vs baseline: 1.7170x; 1.0950x over previous
#include <cuda_runtime.h>
#include <cuda_fp16.h>
#include <cstdint>
#include <cstddef>
#include <math.h>

// ---------------------------------------------------------------------------
// MoE layer, legacy tensor path, fp16 mma.sync.m16n8k16 + ldmatrix frag loads.
//   prep(init + x->fp16 + W1,W2 transpose->[n][k] fp16, ONE launch)
//   -> router -> scan_scatter(1 blk)
//   -> GEMM1 (gather xh, fp16 mma, +b1, gelu) -> g_Hh (fp16)   [launch #3]
//   -> GEMM2 (g_Hh @ W2t + b2)               -> g_Y  (f32)
//   -> combine
// GEMMs: 128x128x32 tiles, warp tile 32x64, 3-stage cp.async, 62KB smem/CTA,
// fragments loaded via ldmatrix.m8n8.x4 (6 instr/warp/kk vs 24 scalar LDS).
// ---------------------------------------------------------------------------

constexpr int HID_ = 1024;
constexpr int FFN_ = 4096;
constexpr int NE_  = 8;
constexpr int T_   = 4096;

constexpr int BM = 128, BN = 128, BK = 32;     // BK in halves (k-elements)
constexpr int STAGES = 3;
constexpr int STRD = 40;                       // halves per smem row (32 + 8 pad) = 80B
constexpr int MAX_SLOTS = T_ * 2 + NE_ * BM;   // 9216
constexpr int ROW_TILES = MAX_SLOTS / BM;      // 72

constexpr uint32_t ABUF = 2u * BM * STRD;      // 10240 B per A stage
constexpr uint32_t BBUF = 2u * BN * STRD;      // 10240 B per B stage
constexpr int SOFF_BIAS = STAGES * (int)(ABUF + BBUF);    // 61440
constexpr int SMEM_BYTES = SOFF_BIAS + BN * 4;            // 61952

// prep grid segmentation
constexpr int TILES1 = NE_ * (HID_ / 32) * (FFN_ / 32);   // 32768
constexpr int TILES2 = NE_ * (FFN_ / 32) * (HID_ / 32);   // 32768
constexpr int XB     = T_ * HID_ / 1024;                  // 4096
constexpr int IB     = (MAX_SLOTS + 255) / 256;           // 36
constexpr int PREP_GRID = TILES1 + TILES2 + XB + IB;

// ---------------- scratch ---------------------------------------------------
__device__ __half g_xh[(size_t)T_ * HID_];              // x  -> fp16
__device__ __half g_W1t[(size_t)NE_ * FFN_ * HID_];     // W1^T: [e][n(FFN)][k(HID)]
__device__ __half g_W2t[(size_t)NE_ * HID_ * FFN_];     // W2^T: [e][n(HID)][k(FFN)]
__device__ __half g_Hh[(size_t)MAX_SLOTS * FFN_];       // GEMM1 out (fp16)
__device__ float  g_Y[(size_t)MAX_SLOTS * HID_];        // GEMM2 out (f32)
__device__ int    g_slot_tok[MAX_SLOTS];
__device__ int    g_tok_slot[T_ * 2];
__device__ int    g_top_i[T_ * 2];
__device__ float  g_top_w[T_ * 2];
__device__ int    g_counts[NE_];
__device__ int    g_poff[NE_ + 1];

// ---------------- helpers ---------------------------------------------------
__device__ __forceinline__ void mma_f16(float* c, const uint32_t* a, const uint32_t* b) {
    asm volatile(
        "mma.sync.aligned.m16n8k16.row.col.f32.f16.f16.f32 "
        "{%0,%1,%2,%3}, {%4,%5,%6,%7}, {%8,%9}, {%0,%1,%2,%3};"
        : "+f"(c[0]), "+f"(c[1]), "+f"(c[2]), "+f"(c[3])
        : "r"(a[0]), "r"(a[1]), "r"(a[2]), "r"(a[3]),
          "r"(b[0]), "r"(b[1]));
}
__device__ __forceinline__ void ldsm_x4(uint32_t* r, uint32_t smem_addr) {
    asm volatile("ldmatrix.sync.aligned.m8n8.x4.shared.b16 {%0,%1,%2,%3}, [%4];"
                 : "=r"(r[0]), "=r"(r[1]), "=r"(r[2]), "=r"(r[3])
                 : "r"(smem_addr));
}
__device__ __forceinline__ void cp16(uint32_t smem_addr, const void* gptr, int src_bytes) {
    asm volatile("cp.async.cg.shared.global [%0], [%1], 16, %2;"
                 :: "r"(smem_addr), "l"(gptr), "r"(src_bytes) : "memory");
}
__device__ __forceinline__ float gelu_exact(float v) {
    return 0.5f * v * (1.0f + erff(v * 0.70710678118654752440f));
}

// ---------------- prep: init + cvt x + transpose-cvt W1,W2 (one launch) -----
__device__ __forceinline__ void transpose_tile(const float* __restrict__ W,
                                               __half* __restrict__ Wt,
                                               int K, int N, int tileIdx,
                                               __half (*tile)[33], int tid) {
    const int tilesPerE = (K / 32) * (N / 32);
    const int e  = tileIdx / tilesPerE;
    const int rm = tileIdx % tilesPerE;
    const int k0 = (rm / (N / 32)) * 32;
    const int n0 = (rm % (N / 32)) * 32;
    const float* src = W + (size_t)e * K * N;
    __half* dst = Wt + (size_t)e * N * K;
    const int tx = tid & 31, ty = tid >> 5;         // 32 x 8
#pragma unroll
    for (int j = 0; j < 4; j++) {
        int k = k0 + ty + 8 * j;
        tile[ty + 8 * j][tx] = __float2half_rn(src[(size_t)k * N + n0 + tx]);
    }
    __syncthreads();
#pragma unroll
    for (int j = 0; j < 4; j++) {
        int n = n0 + ty + 8 * j;
        dst[(size_t)n * K + k0 + tx] = tile[tx][ty + 8 * j];
    }
}

__global__ void prep_kernel(const float* __restrict__ x,
                            const float* __restrict__ W1,
                            const float* __restrict__ W2) {
    __shared__ __half tile[32][33];
    const int bid = blockIdx.x, tid = threadIdx.x;
    if (bid < TILES1) {
        transpose_tile(W1, g_W1t, HID_, FFN_, bid, tile, tid);
    } else if (bid < TILES1 + TILES2) {
        transpose_tile(W2, g_W2t, FFN_, HID_, bid - TILES1, tile, tid);
    } else if (bid < TILES1 + TILES2 + XB) {
        int i = (bid - TILES1 - TILES2) * 256 + tid;      // float4 index
        const float4 v = ((const float4*)x)[i];
        __half2* out = (__half2*)g_xh;
        out[i * 2]     = __floats2half2_rn(v.x, v.y);
        out[i * 2 + 1] = __floats2half2_rn(v.z, v.w);
    } else {
        int i = (bid - TILES1 - TILES2 - XB) * 256 + tid;
        if (i < MAX_SLOTS) g_slot_tok[i] = -1;
        if (i < NE_) g_counts[i] = 0;
    }
}

// ---------------- router ----------------------------------------------------
__global__ void router_kernel(const float* __restrict__ x, const float* __restrict__ Wr) {
    int gw = (blockIdx.x * blockDim.x + threadIdx.x) >> 5;
    int lane = threadIdx.x & 31;
    if (gw >= T_) return;
    const float* xr = x + (size_t)gw * HID_;
    float acc[NE_];
#pragma unroll
    for (int e = 0; e < NE_; e++) acc[e] = 0.f;
    for (int j = lane; j < HID_; j += 32) {
        float xv = xr[j];
        const float4* w4 = (const float4*)(Wr + (size_t)j * NE_);
        float4 a = w4[0], b = w4[1];
        acc[0] += xv * a.x; acc[1] += xv * a.y; acc[2] += xv * a.z; acc[3] += xv * a.w;
        acc[4] += xv * b.x; acc[5] += xv * b.y; acc[6] += xv * b.z; acc[7] += xv * b.w;
    }
#pragma unroll
    for (int off = 16; off > 0; off >>= 1)
#pragma unroll
        for (int e = 0; e < NE_; e++)
            acc[e] += __shfl_xor_sync(0xffffffffu, acc[e], off);
    if (lane == 0) {
        int i0 = 0;
#pragma unroll
        for (int e = 1; e < NE_; e++) if (acc[e] > acc[i0]) i0 = e;   // ties keep low idx
        int i1 = (i0 == 0) ? 1 : 0;
#pragma unroll
        for (int e = 0; e < NE_; e++) if (e != i0 && acc[e] > acc[i1]) i1 = e;
        float d = acc[i1] - acc[i0];
        float w1v = 1.f / (1.f + expf(-d));      // sigmoid == renorm top-2 softmax
        float w0v = 1.f - w1v;
        g_top_i[2 * gw] = i0;  g_top_i[2 * gw + 1] = i1;
        g_top_w[2 * gw] = w0v; g_top_w[2 * gw + 1] = w1v;
        atomicAdd(&g_counts[i0], 1);
        atomicAdd(&g_counts[i1], 1);
    }
}

// ---------------- scan + scatter (one block) --------------------------------
__global__ void scan_scatter_kernel() {
    __shared__ int fill_s[NE_];
    __shared__ int poff_s[NE_ + 1];
    const int tid = threadIdx.x;
    if (tid == 0) {
        int o = 0;
#pragma unroll
        for (int e = 0; e < NE_; e++) {
            poff_s[e] = o; g_poff[e] = o;
            o += ((g_counts[e] + BM - 1) / BM) * BM;
        }
        poff_s[NE_] = o; g_poff[NE_] = o;
    }
    if (tid < NE_) fill_s[tid] = 0;
    __syncthreads();
    for (int tk = tid; tk < T_ * 2; tk += 256) {
        int e = g_top_i[tk];
        int p = atomicAdd(&fill_s[e], 1);
        int s = poff_s[e] + p;
        g_slot_tok[s] = tk >> 1;
        g_tok_slot[tk] = s;
    }
}

// ---------------- grouped GEMM (fp16 m16n8k16, ldmatrix, 32x64 warp) --------
template <int KD, int ND, bool FFN1>
__global__ void __launch_bounds__(256, 2)
moe_gemm_kernel(const __half* __restrict__ Aall,
                const __half* __restrict__ Wt,
                const float* __restrict__ bias) {
    extern __shared__ char smem_raw[];
    __half* As_base = (__half*)smem_raw;                          // [STAGES][BM][STRD]
    __half* Bs_base = (__half*)(smem_raw + STAGES * (int)ABUF);   // [STAGES][BN][STRD]
    float*  bias_s  = (float*)(smem_raw + SOFF_BIAS);             // [BN]

    const int row0 = blockIdx.x * BM;
    if (row0 >= g_poff[NE_]) return;
    int e = 0;
#pragma unroll
    for (int i = 1; i < NE_; i++) if (g_poff[i] <= row0) e = i;

    const __half* Wb = Wt + (size_t)e * KD * ND;   // [ND][KD]
    const int n0 = blockIdx.y * BN;
    const int tid = threadIdx.x;

    if (tid < BN) bias_s[tid] = bias[(size_t)e * ND + n0 + tid];

    // ---- cp.async assignments: rows of 32 halves = 4 x 16B chunks ----
    const __half* agp[2]; uint32_t asmem[2]; int apred[2];
#pragma unroll
    for (int it = 0; it < 2; it++) {
        int q = tid + it * 256;
        int r = q >> 2, c4 = q & 3;
        int s = row0 + r;
        int pred = 16;
        const __half* gp;
        if (FFN1) {
            int tok = g_slot_tok[s];
            if (tok < 0) { pred = 0; tok = 0; }   // pad row -> zero-fill
            gp = Aall + (size_t)tok * KD;
        } else {
            gp = Aall + (size_t)s * KD;
        }
        agp[it] = gp + c4 * 8;
        apred[it] = pred;
        asmem[it] = (uint32_t)__cvta_generic_to_shared(&As_base[r * STRD + c4 * 8]);
    }
    const __half* bgp[2]; uint32_t bsmem[2];
#pragma unroll
    for (int it = 0; it < 2; it++) {
        int q = tid + it * 256;
        int r = q >> 2, c4 = q & 3;
        bgp[it] = Wb + (size_t)(n0 + r) * KD + c4 * 8;
        bsmem[it] = (uint32_t)__cvta_generic_to_shared(&Bs_base[r * STRD + c4 * 8]);
    }

    const int lane = tid & 31, warp = tid >> 5;
    const int wm = warp >> 1, wn = warp & 1;   // 4 x 2 warp grid; 32x64 per warp
    const int gg = lane >> 2, tt = lane & 3;

    // ---- ldmatrix per-lane address offsets (bytes, within one stage) ----
    // lane -> matrix m = lane>>3, row-in-matrix rr = lane&7
    const int lm = lane >> 3, rr = lane & 7;
    const uint32_t as_u32 = (uint32_t)__cvta_generic_to_shared(As_base);
    const uint32_t bs_u32 = (uint32_t)__cvta_generic_to_shared(Bs_base);
    // A (mi, k-half): m0 = rows+0 klo, m1 = rows+8 klo, m2 = rows+0 khi, m3 = rows+8 khi
    uint32_t aoff[2];
#pragma unroll
    for (int mi = 0; mi < 2; mi++) {
        int row = wm * 32 + mi * 16 + (lm & 1) * 8 + rr;
        int col = (lm >> 1) * 8;
        aoff[mi] = (uint32_t)((row * STRD + col) * 2);
    }
    // B (j covers ni=2j,2j+1): m0 = n(2j) klo, m1 = n(2j) khi, m2 = n(2j+1) klo, m3 = n(2j+1) khi
    uint32_t boff[4];
#pragma unroll
    for (int j = 0; j < 4; j++) {
        int n = wn * 64 + (2 * j + (lm >> 1)) * 8 + rr;
        int col = (lm & 1) * 8;
        boff[j] = (uint32_t)((n * STRD + col) * 2);
    }

    float acc[2][8][4];
#pragma unroll
    for (int a = 0; a < 2; a++)
#pragma unroll
        for (int b = 0; b < 8; b++)
#pragma unroll
            for (int c = 0; c < 4; c++) acc[a][b][c] = 0.f;

    const int KT = KD / BK;   // 32 (GEMM1) or 128 (GEMM2)

    // prefetch stages 0,1
#pragma unroll
    for (int s = 0; s < STAGES - 1; s++) {
#pragma unroll
        for (int it = 0; it < 2; it++)
            cp16(asmem[it] + s * ABUF, agp[it] + (size_t)s * BK, apred[it]);
#pragma unroll
        for (int it = 0; it < 2; it++)
            cp16(bsmem[it] + s * BBUF, bgp[it] + (size_t)s * BK, 16);
        asm volatile("cp.async.commit_group;" ::: "memory");
    }

    for (int kt = 0; kt < KT; ++kt) {
        if (kt + 1 < KT) asm volatile("cp.async.wait_group 1;" ::: "memory");
        else             asm volatile("cp.async.wait_group 0;" ::: "memory");
        __syncthreads();   // single barrier per k-iter; buf (kt+2)%3 reusable after it

        if (kt + 2 < KT) {
            const int sb = (kt + 2) % STAGES;
            const uint32_t ao = sb * ABUF, bo = sb * BBUF;
#pragma unroll
            for (int it = 0; it < 2; it++)
                cp16(asmem[it] + ao, agp[it] + (size_t)(kt + 2) * BK, apred[it]);
#pragma unroll
            for (int it = 0; it < 2; it++)
                cp16(bsmem[it] + bo, bgp[it] + (size_t)(kt + 2) * BK, 16);
            asm volatile("cp.async.commit_group;" ::: "memory");
        }

        const int buf = kt % STAGES;
        const uint32_t abase = as_u32 + buf * ABUF;
        const uint32_t bbase = bs_u32 + buf * BBUF;
#pragma unroll
        for (int kk = 0; kk < BK; kk += 16) {     // two m16n8k16 steps per buffer
            uint32_t af[2][4], bf[8][2];
#pragma unroll
            for (int mi = 0; mi < 2; mi++)
                ldsm_x4(af[mi], abase + aoff[mi] + kk * 2);
#pragma unroll
            for (int j = 0; j < 4; j++) {
                uint32_t r4[4];
                ldsm_x4(r4, bbase + boff[j] + kk * 2);
                bf[2 * j][0] = r4[0]; bf[2 * j][1] = r4[1];
                bf[2 * j + 1][0] = r4[2]; bf[2 * j + 1][1] = r4[3];
            }
#pragma unroll
            for (int mi = 0; mi < 2; mi++)
#pragma unroll
                for (int ni = 0; ni < 8; ni++)
                    mma_f16(acc[mi][ni], af[mi], bf[ni]);
        }
    }

    // epilogue: c0/c1 -> row gg cols 2tt/2tt+1 ; c2/c3 -> row gg+8
#pragma unroll
    for (int mi = 0; mi < 2; mi++) {
#pragma unroll
        for (int half = 0; half < 2; half++) {
            int r = row0 + wm * 32 + mi * 16 + gg + half * 8;
#pragma unroll
            for (int ni = 0; ni < 8; ni++) {
                int colL = wn * 64 + ni * 8 + 2 * tt;
                float v0 = acc[mi][ni][half * 2 + 0] + bias_s[colL];
                float v1 = acc[mi][ni][half * 2 + 1] + bias_s[colL + 1];
                if (FFN1) {
                    __half2 hv = __floats2half2_rn(gelu_exact(v0), gelu_exact(v1));
                    *(__half2*)&g_Hh[(size_t)r * ND + n0 + colL] = hv;
                } else {
                    float2 v; v.x = v0; v.y = v1;
                    *(float2*)&g_Y[(size_t)r * ND + n0 + colL] = v;
                }
            }
        }
    }
}

// ---------------- combine ----------------------------------------------------
__global__ void combine_kernel(float* __restrict__ out) {
    int i = blockIdx.x * blockDim.x + threadIdx.x;
    if (i >= T_ * HID_ / 4) return;
    int t = i / (HID_ / 4);
    int c4 = i % (HID_ / 4);
    int s0 = g_tok_slot[2 * t], s1 = g_tok_slot[2 * t + 1];
    float w0 = g_top_w[2 * t], w1 = g_top_w[2 * t + 1];
    float4 y0 = ((const float4*)(g_Y + (size_t)s0 * HID_))[c4];
    float4 y1 = ((const float4*)(g_Y + (size_t)s1 * HID_))[c4];
    float4 r;
    r.x = w0 * y0.x + w1 * y1.x;
    r.y = w0 * y0.y + w1 * y1.y;
    r.z = w0 * y0.z + w1 * y1.z;
    r.w = w0 * y0.w + w1 * y1.w;
    ((float4*)(out + (size_t)t * HID_))[c4] = r;
}

// ---------------- launch ----------------------------------------------------
extern "C" void kernel_launch(void* const* d_in, const int* in_sizes, int n_in,
                              void* d_out, int out_size) {
    (void)in_sizes; (void)n_in; (void)out_size;
    const float* x  = (const float*)d_in[0];
    const float* Wr = (const float*)d_in[1];
    const float* W1 = (const float*)d_in[2];
    const float* b1 = (const float*)d_in[3];
    const float* W2 = (const float*)d_in[4];
    const float* b2 = (const float*)d_in[5];
    float* out = (float*)d_out;

    cudaFuncSetAttribute(moe_gemm_kernel<HID_, FFN_, true>,
                         cudaFuncAttributeMaxDynamicSharedMemorySize, SMEM_BYTES);
    cudaFuncSetAttribute(moe_gemm_kernel<FFN_, HID_, false>,
                         cudaFuncAttributeMaxDynamicSharedMemorySize, SMEM_BYTES);

    __half* xh;  cudaGetSymbolAddress((void**)&xh,  g_xh);
    __half* w1t; cudaGetSymbolAddress((void**)&w1t, g_W1t);
    __half* w2t; cudaGetSymbolAddress((void**)&w2t, g_W2t);
    __half* hh;  cudaGetSymbolAddress((void**)&hh,  g_Hh);

    // launches: 0:prep 1:router 2:scan_scatter 3:GEMM1 4:GEMM2 5:combine
    prep_kernel<<<PREP_GRID, 256>>>(x, W1, W2);
    router_kernel<<<(T_ * 32 + 255) / 256, 256>>>(x, Wr);
    scan_scatter_kernel<<<1, 256>>>();

    moe_gemm_kernel<HID_, FFN_, true>
        <<<dim3(ROW_TILES, FFN_ / BN), 256, SMEM_BYTES>>>(xh, w1t, b1);
    moe_gemm_kernel<FFN_, HID_, false>
        <<<dim3(ROW_TILES, HID_ / BN), 256, SMEM_BYTES>>>(hh, w2t, b2);

    combine_kernel<<<(T_ * HID_ / 4 + 255) / 256, 256>>>(out);
}